// round 10
// baseline (speedup 1.0000x reference)
#include <cuda_runtime.h>
#include <cuda_bf16.h>
#include <cstdint>

#define K_DIM   8192
#define B_DIM   256
#define OUT_DIM 8192
#define BM      128
#define BN      128
#define KC      32
#define NT      (K_DIM / KC)          // 256 stages
#define RSTRIDE 80                    // bytes per smem row (32 bf16 + 16B pad)
#define SPLIT_BYTES (128 * RSTRIDE)   // 10240 per split tile
#define STAGE_BYTES (4 * SPLIT_BYTES) // A_hi|A_lo|B_hi|B_lo = 40960
#define NSTAGE  3
#define DSMEM_BYTES (NSTAGE * STAGE_BYTES)  // 122880

#define NTHREADS 384                  // 8 consumer warps + 4 producer warps

// ---------------- scratch: bf16 split of x ----------------
__device__ __nv_bfloat16 g_x_hi[(size_t)B_DIM * K_DIM];
__device__ __nv_bfloat16 g_x_lo[(size_t)B_DIM * K_DIM];

// ---------------- helpers ----------------
__device__ __forceinline__ uint32_t smem_u32(const void* p) {
    uint32_t a;
    asm("{ .reg .u64 t; cvta.to.shared.u64 t, %1; cvt.u32.u64 %0, t; }" : "=r"(a) : "l"(p));
    return a;
}
__device__ __forceinline__ uint32_t cvt2(float hiVal, float loVal) {
    uint32_t r;
    asm("cvt.rn.bf16x2.f32 %0, %1, %2;" : "=r"(r) : "f"(hiVal), "f"(loVal));
    return r;
}

#define LDSM4(r0, r1, r2, r3, addr) \
    asm volatile("ldmatrix.sync.aligned.m8n8.x4.shared.b16 {%0,%1,%2,%3}, [%4];" \
                 : "=r"(r0), "=r"(r1), "=r"(r2), "=r"(r3) : "r"(addr))

#define MMA(c, a, b) \
    asm volatile("mma.sync.aligned.m16n8k16.row.col.f32.bf16.bf16.f32 " \
                 "{%0,%1,%2,%3}, {%4,%5,%6,%7}, {%8,%9}, {%0,%1,%2,%3};" \
                 : "+f"((c)[0]), "+f"((c)[1]), "+f"((c)[2]), "+f"((c)[3]) \
                 : "r"((a)[0]), "r"((a)[1]), "r"((a)[2]), "r"((a)[3]), \
                   "r"((b)[0]), "r"((b)[1]))

#define CP_ASYNC16(dst, src) \
    asm volatile("cp.async.cg.shared.global [%0], [%1], 16;" :: "r"(dst), "l"(src) : "memory")
#define CP_COMMIT() asm volatile("cp.async.commit_group;" ::: "memory")
#define CP_WAIT0()  asm volatile("cp.async.wait_group 0;" ::: "memory")

// named producer/consumer barriers (count = all 384 threads)
#define BAR_SYNC(id)   asm volatile("bar.sync %0, %1;"   :: "r"(id), "n"(NTHREADS) : "memory")
#define BAR_ARRIVE(id) asm volatile("bar.arrive %0, %1;" :: "r"(id), "n"(NTHREADS) : "memory")
// READY(s) = 1+s : producers arrive, consumers sync
// FREE(s)  = 4+s : consumers arrive, producers sync

// ---------------- kernel 1: split x into bf16 hi/lo ----------------
__global__ __launch_bounds__(256)
void convert_x_kernel(const float* __restrict__ x) {
    size_t i = ((size_t)blockIdx.x * 256 + threadIdx.x) * 8;
    float4 a = *reinterpret_cast<const float4*>(x + i);
    float4 b = *reinterpret_cast<const float4*>(x + i + 4);
    uint32_t h0 = cvt2(a.y, a.x), h1 = cvt2(a.w, a.z);
    uint32_t h2 = cvt2(b.y, b.x), h3 = cvt2(b.w, b.z);
    float l0 = a.x - __uint_as_float(h0 << 16);
    float l1 = a.y - __uint_as_float(h0 & 0xffff0000u);
    float l2 = a.z - __uint_as_float(h1 << 16);
    float l3 = a.w - __uint_as_float(h1 & 0xffff0000u);
    float l4 = b.x - __uint_as_float(h2 << 16);
    float l5 = b.y - __uint_as_float(h2 & 0xffff0000u);
    float l6 = b.z - __uint_as_float(h3 << 16);
    float l7 = b.w - __uint_as_float(h3 & 0xffff0000u);
    *reinterpret_cast<uint4*>(g_x_hi + i) = make_uint4(h0, h1, h2, h3);
    *reinterpret_cast<uint4*>(g_x_lo + i) =
        make_uint4(cvt2(l1, l0), cvt2(l3, l2), cvt2(l5, l4), cvt2(l7, l6));
}

// ---------------- kernel 2: warp-specialized split-bf16 GEMM + IBP ----------------
__global__ __launch_bounds__(NTHREADS, 1)
void abstract_linear_mma_kernel(const float* __restrict__ low,
                                const float* __restrict__ high,
                                const float* __restrict__ W,
                                const float* __restrict__ bias,
                                float* __restrict__ y,
                                float* __restrict__ low_out,
                                float* __restrict__ high_out)
{
    extern __shared__ __align__(128) char dsm[];
    const uint32_t sbase = smem_u32(dsm);

    const int tid  = threadIdx.x;
    const int lane = tid & 31;
    const int wid  = tid >> 5;       // 0..11
    const int nBase = blockIdx.x * BN;
    const int mBase = blockIdx.y * BM;
    const bool doB = (blockIdx.y == 0);

    if (wid < 8) {
        // ================= CONSUMERS: pure LDSM + MMA =================
        const int wm = wid >> 2;   // 0..1  (64 m-rows each)
        const int wn = wid & 3;    // 0..3  (32 n-cols each)

        const uint32_t aOff = (uint32_t)(wm * 64 + (lane & 15)) * RSTRIDE + (lane >> 4) * 16;
        const uint32_t bOff = (uint32_t)(wn * 32 + (lane & 7) + ((lane >> 4) & 1) * 8) * RSTRIDE
                            + ((lane >> 3) & 1) * 16;

        float acc[4][4][4];
        #pragma unroll
        for (int i = 0; i < 4; ++i)
            #pragma unroll
            for (int j = 0; j < 4; ++j)
                #pragma unroll
                for (int r = 0; r < 4; ++r) acc[i][j][r] = 0.f;

        #pragma unroll 1
        for (int kt = 0; kt < NT; ++kt) {
            const int stage = kt % NSTAGE;
            BAR_SYNC(1 + stage);                       // wait data ready
            const uint32_t A_hi = sbase + stage * STAGE_BYTES;
            const uint32_t A_lo = A_hi + SPLIT_BYTES;
            const uint32_t B_hi = A_hi + 2 * SPLIT_BYTES;
            const uint32_t B_lo = A_hi + 3 * SPLIT_BYTES;
            #pragma unroll
            for (int k16 = 0; k16 < 2; ++k16) {
                uint32_t aH[4][4], aL[4][4], bH[4][2], bL[4][2];
                #pragma unroll
                for (int mf = 0; mf < 4; ++mf) {
                    LDSM4(aH[mf][0], aH[mf][1], aH[mf][2], aH[mf][3],
                          A_hi + aOff + mf * (16 * RSTRIDE) + k16 * 32);
                    LDSM4(aL[mf][0], aL[mf][1], aL[mf][2], aL[mf][3],
                          A_lo + aOff + mf * (16 * RSTRIDE) + k16 * 32);
                }
                #pragma unroll
                for (int p = 0; p < 2; ++p) {
                    uint32_t r0, r1, r2, r3;
                    LDSM4(r0, r1, r2, r3, B_hi + bOff + p * (16 * RSTRIDE) + k16 * 32);
                    bH[2 * p][0] = r0; bH[2 * p][1] = r1;
                    bH[2 * p + 1][0] = r2; bH[2 * p + 1][1] = r3;
                    LDSM4(r0, r1, r2, r3, B_lo + bOff + p * (16 * RSTRIDE) + k16 * 32);
                    bL[2 * p][0] = r0; bL[2 * p][1] = r1;
                    bL[2 * p + 1][0] = r2; bL[2 * p + 1][1] = r3;
                }
                #pragma unroll
                for (int mf = 0; mf < 4; ++mf)
                    #pragma unroll
                    for (int nf = 0; nf < 4; ++nf) MMA(acc[mf][nf], aH[mf], bH[nf]);
                #pragma unroll
                for (int mf = 0; mf < 4; ++mf)
                    #pragma unroll
                    for (int nf = 0; nf < 4; ++nf) MMA(acc[mf][nf], aH[mf], bL[nf]);
                #pragma unroll
                for (int mf = 0; mf < 4; ++mf)
                    #pragma unroll
                    for (int nf = 0; nf < 4; ++nf) MMA(acc[mf][nf], aL[mf], bH[nf]);
            }
            BAR_ARRIVE(4 + stage);                     // stage consumed
        }

        // epilogue: y = acc + bias
        #pragma unroll
        for (int mf = 0; mf < 4; ++mf) {
            const int r0 = mBase + wm * 64 + mf * 16 + (lane >> 2);
            #pragma unroll
            for (int nf = 0; nf < 4; ++nf) {
                const int c = nBase + wn * 32 + nf * 8 + (lane & 3) * 2;
                const float2 bv = *reinterpret_cast<const float2*>(bias + c);
                float2 o0 = make_float2(acc[mf][nf][0] + bv.x, acc[mf][nf][1] + bv.y);
                float2 o1 = make_float2(acc[mf][nf][2] + bv.x, acc[mf][nf][3] + bv.y);
                *reinterpret_cast<float2*>(y + (size_t)r0 * OUT_DIM + c) = o0;
                *reinterpret_cast<float2*>(y + (size_t)(r0 + 8) * OUT_DIM + c) = o1;
            }
        }
    } else {
        // ================= PRODUCERS: x cp.async, W LDG->split->STS, bounds =================
        const int ptid = tid - 256;                    // 0..127

        // x loader: thread -> (split, 2 rows)
        const int xsp = ptid >> 6;                     // 0: hi, 1: lo
        const int xr0 = (ptid & 63) * 2;
        const __nv_bfloat16* xg = (xsp ? g_x_lo : g_x_hi) + (size_t)(mBase + xr0) * K_DIM;
        const uint32_t xdstBase = (uint32_t)xsp * SPLIT_BYTES + (uint32_t)xr0 * RSTRIDE;

        // W loader: thread -> one full row (32 elems)
        const float* wg = W + (size_t)(nBase + ptid) * K_DIM;
        const uint32_t wsts = (uint32_t)ptid * RSTRIDE;

        float boundLo = 0.f, boundHi = 0.f;
        float4 wvC[2], wvC2[2], wvN[2], wvN2[2];       // 32 floats in two halves

        auto cpX = [&](int stage, int kt) {
            uint32_t dst = sbase + stage * STAGE_BYTES + xdstBase;
            const __nv_bfloat16* src = xg + kt * KC;
            CP_ASYNC16(dst,      src);      CP_ASYNC16(dst + 16, src + 8);
            CP_ASYNC16(dst + 32, src + 16); CP_ASYNC16(dst + 48, src + 24);
            dst += RSTRIDE; src += K_DIM;
            CP_ASYNC16(dst,      src);      CP_ASYNC16(dst + 16, src + 8);
            CP_ASYNC16(dst + 32, src + 16); CP_ASYNC16(dst + 48, src + 24);
            CP_COMMIT();
        };

        auto loadW = [&](int kt, float4* v, float4* v2) {
            v[0]  = *reinterpret_cast<const float4*>(wg + (size_t)kt * KC);
            v[1]  = *reinterpret_cast<const float4*>(wg + (size_t)kt * KC + 4);
            v2[0] = *reinterpret_cast<const float4*>(wg + (size_t)kt * KC + 8);
            v2[1] = *reinterpret_cast<const float4*>(wg + (size_t)kt * KC + 12);
        };
        auto loadW2 = [&](int kt, float4* v, float4* v2) {
            v[0]  = *reinterpret_cast<const float4*>(wg + (size_t)kt * KC + 16);
            v[1]  = *reinterpret_cast<const float4*>(wg + (size_t)kt * KC + 20);
            v2[0] = *reinterpret_cast<const float4*>(wg + (size_t)kt * KC + 24);
            v2[1] = *reinterpret_cast<const float4*>(wg + (size_t)kt * KC + 28);
        };

        auto stashHalf = [&](int stage, int kt, int half, const float4* v, const float4* v2) {
            char* bHp = dsm + (size_t)stage * STAGE_BYTES + 2 * SPLIT_BYTES + wsts + half * 32;
            char* bLp = bHp + SPLIT_BYTES;
            #pragma unroll
            for (int i = 0; i < 2; ++i) {
                const float4 a = (i == 0) ? v[0] : v2[0];
                const float4 b = (i == 0) ? v[1] : v2[1];
                uint32_t h0 = cvt2(a.y, a.x), h1 = cvt2(a.w, a.z);
                uint32_t h2 = cvt2(b.y, b.x), h3 = cvt2(b.w, b.z);
                float l0 = a.x - __uint_as_float(h0 << 16);
                float l1 = a.y - __uint_as_float(h0 & 0xffff0000u);
                float l2 = a.z - __uint_as_float(h1 << 16);
                float l3 = a.w - __uint_as_float(h1 & 0xffff0000u);
                float l4 = b.x - __uint_as_float(h2 << 16);
                float l5 = b.y - __uint_as_float(h2 & 0xffff0000u);
                float l6 = b.z - __uint_as_float(h3 << 16);
                float l7 = b.w - __uint_as_float(h3 & 0xffff0000u);
                *reinterpret_cast<uint4*>(bHp + i * 16) = make_uint4(h0, h1, h2, h3);
                *reinterpret_cast<uint4*>(bLp + i * 16) =
                    make_uint4(cvt2(l1, l0), cvt2(l3, l2), cvt2(l5, l4), cvt2(l7, l6));
                if (doB) {
                    const float* lp = low  + kt * KC + half * 16 + i * 8;
                    const float* hp = high + kt * KC + half * 16 + i * 8;
                    const float4 la = *reinterpret_cast<const float4*>(lp);
                    const float4 lb = *reinterpret_cast<const float4*>(lp + 4);
                    const float4 ha = *reinterpret_cast<const float4*>(hp);
                    const float4 hb = *reinterpret_cast<const float4*>(hp + 4);
                    float p, q;
                    p = a.x * la.x; q = a.x * ha.x; boundLo += fminf(p, q); boundHi += fmaxf(p, q);
                    p = a.y * la.y; q = a.y * ha.y; boundLo += fminf(p, q); boundHi += fmaxf(p, q);
                    p = a.z * la.z; q = a.z * ha.z; boundLo += fminf(p, q); boundHi += fmaxf(p, q);
                    p = a.w * la.w; q = a.w * ha.w; boundLo += fminf(p, q); boundHi += fmaxf(p, q);
                    p = b.x * lb.x; q = b.x * hb.x; boundLo += fminf(p, q); boundHi += fmaxf(p, q);
                    p = b.y * lb.y; q = b.y * hb.y; boundLo += fminf(p, q); boundHi += fmaxf(p, q);
                    p = b.z * lb.z; q = b.z * hb.z; boundLo += fminf(p, q); boundHi += fmaxf(p, q);
                    p = b.w * lb.w; q = b.w * hb.w; boundLo += fminf(p, q); boundHi += fmaxf(p, q);
                }
            }
        };

        // prologue: W for stage 0 in registers
        loadW(0, wvC, wvC2);
        loadW2(0, wvN, wvN2);

        #pragma unroll 1
        for (int kt = 0; kt < NT; ++kt) {
            const int stage = kt % NSTAGE;
            if (kt >= NSTAGE) BAR_SYNC(4 + stage);      // wait stage free
            cpX(stage, kt);                             // x in flight
            stashHalf(stage, kt, 0, wvC, wvC2);
            stashHalf(stage, kt, 1, wvN, wvN2);
            if (kt + 1 < NT) {                          // prefetch next W (overlaps wait)
                loadW(kt + 1, wvC, wvC2);
                loadW2(kt + 1, wvN, wvN2);
            }
            CP_WAIT0();                                 // this stage's x landed
            BAR_ARRIVE(1 + stage);                      // publish stage
        }

        // epilogue: bounds (each producer thread owns one full W row)
        if (doB) {
            const int r = nBase + ptid;
            const float bb = bias[r];
            low_out[r]  = boundLo + bb;
            high_out[r] = boundHi + bb;
        }
    }
}

extern "C" void kernel_launch(void* const* d_in, const int* in_sizes, int n_in,
                              void* d_out, int out_size) {
    const float* x    = (const float*)d_in[0];
    const float* low  = (const float*)d_in[1];
    const float* high = (const float*)d_in[2];
    const float* W    = (const float*)d_in[3];
    const float* bias = (const float*)d_in[4];

    float* y        = (float*)d_out;
    float* low_out  = y + (size_t)B_DIM * OUT_DIM;
    float* high_out = low_out + OUT_DIM;

    cudaFuncSetAttribute(abstract_linear_mma_kernel,
                         cudaFuncAttributeMaxDynamicSharedMemorySize, DSMEM_BYTES);

    convert_x_kernel<<<(B_DIM * K_DIM) / (256 * 8), 256>>>(x);

    dim3 grid(OUT_DIM / BN, B_DIM / BM);  // (64, 2) = 128 CTAs
    abstract_linear_mma_kernel<<<grid, NTHREADS, DSMEM_BYTES>>>(low, high, W, bias,
                                                                y, low_out, high_out);
}

// round 11
// speedup vs baseline: 1.2867x; 1.2867x over previous
#include <cuda_runtime.h>
#include <cuda_bf16.h>
#include <cstdint>

#define K_DIM   8192
#define B_DIM   256
#define OUT_DIM 8192
#define BM      128
#define BN      128
#define KC      32
#define NT      (K_DIM / KC)          // 256 stages
#define RSTRIDE 80                    // bytes per smem row (32 bf16 + 16B pad)
#define SPLIT_BYTES (128 * RSTRIDE)   // 10240 per split tile
#define STAGE_BYTES (4 * SPLIT_BYTES) // A_hi|A_lo|B_hi|B_lo = 40960
#define NSTAGE  5
#define DSMEM_BYTES (NSTAGE * STAGE_BYTES)  // 204800

// ---------------- scratch: bf16 splits ----------------
__device__ __nv_bfloat16 g_x_hi[(size_t)B_DIM * K_DIM];
__device__ __nv_bfloat16 g_x_lo[(size_t)B_DIM * K_DIM];
__device__ __nv_bfloat16 g_w_hi[(size_t)OUT_DIM * K_DIM];
__device__ __nv_bfloat16 g_w_lo[(size_t)OUT_DIM * K_DIM];

// ---------------- helpers ----------------
__device__ __forceinline__ uint32_t smem_u32(const void* p) {
    uint32_t a;
    asm("{ .reg .u64 t; cvta.to.shared.u64 t, %1; cvt.u32.u64 %0, t; }" : "=r"(a) : "l"(p));
    return a;
}
__device__ __forceinline__ uint32_t cvt2(float hiVal, float loVal) {
    uint32_t r;
    asm("cvt.rn.bf16x2.f32 %0, %1, %2;" : "=r"(r) : "f"(hiVal), "f"(loVal));
    return r;
}

#define LDSM4(r0, r1, r2, r3, addr) \
    asm volatile("ldmatrix.sync.aligned.m8n8.x4.shared.b16 {%0,%1,%2,%3}, [%4];" \
                 : "=r"(r0), "=r"(r1), "=r"(r2), "=r"(r3) : "r"(addr))

#define MMA(c, a, b) \
    asm volatile("mma.sync.aligned.m16n8k16.row.col.f32.bf16.bf16.f32 " \
                 "{%0,%1,%2,%3}, {%4,%5,%6,%7}, {%8,%9}, {%0,%1,%2,%3};" \
                 : "+f"((c)[0]), "+f"((c)[1]), "+f"((c)[2]), "+f"((c)[3]) \
                 : "r"((a)[0]), "r"((a)[1]), "r"((a)[2]), "r"((a)[3]), \
                   "r"((b)[0]), "r"((b)[1]))

#define CP_ASYNC16(dst, src) \
    asm volatile("cp.async.cg.shared.global [%0], [%1], 16;" :: "r"(dst), "l"(src) : "memory")
#define CP_COMMIT() asm volatile("cp.async.commit_group;" ::: "memory")
#define CP_WAIT3()  asm volatile("cp.async.wait_group 3;" ::: "memory")
#define CP_WAIT0()  asm volatile("cp.async.wait_group 0;" ::: "memory")

// ---------------- kernel 1: split x into bf16 hi/lo ----------------
__global__ __launch_bounds__(256)
void convert_x_kernel(const float* __restrict__ x) {
    size_t i = ((size_t)blockIdx.x * 256 + threadIdx.x) * 8;
    float4 a = *reinterpret_cast<const float4*>(x + i);
    float4 b = *reinterpret_cast<const float4*>(x + i + 4);
    uint32_t h0 = cvt2(a.y, a.x), h1 = cvt2(a.w, a.z);
    uint32_t h2 = cvt2(b.y, b.x), h3 = cvt2(b.w, b.z);
    float l0 = a.x - __uint_as_float(h0 << 16);
    float l1 = a.y - __uint_as_float(h0 & 0xffff0000u);
    float l2 = a.z - __uint_as_float(h1 << 16);
    float l3 = a.w - __uint_as_float(h1 & 0xffff0000u);
    float l4 = b.x - __uint_as_float(h2 << 16);
    float l5 = b.y - __uint_as_float(h2 & 0xffff0000u);
    float l6 = b.z - __uint_as_float(h3 << 16);
    float l7 = b.w - __uint_as_float(h3 & 0xffff0000u);
    *reinterpret_cast<uint4*>(g_x_hi + i) = make_uint4(h0, h1, h2, h3);
    *reinterpret_cast<uint4*>(g_x_lo + i) =
        make_uint4(cvt2(l1, l0), cvt2(l3, l2), cvt2(l5, l4), cvt2(l7, l6));
}

// ---------------- kernel 2: split W into bf16 hi/lo + exact IBP bounds ----------------
// grid: 1024 blocks x 256 threads; block handles 8 W rows.
__global__ __launch_bounds__(256)
void convert_w_kernel(const float* __restrict__ W,
                      const float* __restrict__ low,
                      const float* __restrict__ high,
                      const float* __restrict__ bias,
                      float* __restrict__ low_out,
                      float* __restrict__ high_out) {
    __shared__ float redLo[256], redHi[256];
    const int tid = threadIdx.x;
    const int row0 = blockIdx.x * 8;

    for (int r = 0; r < 8; ++r) {
        const int row = row0 + r;
        const float* wr = W + (size_t)row * K_DIM;
        float accLo = 0.f, accHi = 0.f;
        #pragma unroll
        for (int it = 0; it < 4; ++it) {
            const int c = tid * 8 + it * 2048;
            const float4 a = *reinterpret_cast<const float4*>(wr + c);
            const float4 b = *reinterpret_cast<const float4*>(wr + c + 4);
            const float4 la = *reinterpret_cast<const float4*>(low + c);
            const float4 lb = *reinterpret_cast<const float4*>(low + c + 4);
            const float4 ha = *reinterpret_cast<const float4*>(high + c);
            const float4 hb = *reinterpret_cast<const float4*>(high + c + 4);
            uint32_t h0 = cvt2(a.y, a.x), h1 = cvt2(a.w, a.z);
            uint32_t h2 = cvt2(b.y, b.x), h3 = cvt2(b.w, b.z);
            float l0 = a.x - __uint_as_float(h0 << 16);
            float l1 = a.y - __uint_as_float(h0 & 0xffff0000u);
            float l2 = a.z - __uint_as_float(h1 << 16);
            float l3 = a.w - __uint_as_float(h1 & 0xffff0000u);
            float l4 = b.x - __uint_as_float(h2 << 16);
            float l5 = b.y - __uint_as_float(h2 & 0xffff0000u);
            float l6 = b.z - __uint_as_float(h3 << 16);
            float l7 = b.w - __uint_as_float(h3 & 0xffff0000u);
            *reinterpret_cast<uint4*>(g_w_hi + (size_t)row * K_DIM + c) =
                make_uint4(h0, h1, h2, h3);
            *reinterpret_cast<uint4*>(g_w_lo + (size_t)row * K_DIM + c) =
                make_uint4(cvt2(l1, l0), cvt2(l3, l2), cvt2(l5, l4), cvt2(l7, l6));
            float p, q;
            p = a.x * la.x; q = a.x * ha.x; accLo += fminf(p, q); accHi += fmaxf(p, q);
            p = a.y * la.y; q = a.y * ha.y; accLo += fminf(p, q); accHi += fmaxf(p, q);
            p = a.z * la.z; q = a.z * ha.z; accLo += fminf(p, q); accHi += fmaxf(p, q);
            p = a.w * la.w; q = a.w * ha.w; accLo += fminf(p, q); accHi += fmaxf(p, q);
            p = b.x * lb.x; q = b.x * hb.x; accLo += fminf(p, q); accHi += fmaxf(p, q);
            p = b.y * lb.y; q = b.y * hb.y; accLo += fminf(p, q); accHi += fmaxf(p, q);
            p = b.z * lb.z; q = b.z * hb.z; accLo += fminf(p, q); accHi += fmaxf(p, q);
            p = b.w * lb.w; q = b.w * hb.w; accLo += fminf(p, q); accHi += fmaxf(p, q);
        }
        redLo[tid] = accLo; redHi[tid] = accHi;
        __syncthreads();
        #pragma unroll
        for (int s = 128; s > 0; s >>= 1) {
            if (tid < s) { redLo[tid] += redLo[tid + s]; redHi[tid] += redHi[tid + s]; }
            __syncthreads();
        }
        if (tid == 0) {
            const float bb = bias[row];
            low_out[row]  = redLo[0] + bb;
            high_out[row] = redHi[0] + bb;
        }
        __syncthreads();
    }
}

// ---------------- kernel 3: pure bf16 split GEMM (clean mainloop) ----------------
__global__ __launch_bounds__(256, 1)
void abstract_linear_mma_kernel(const float* __restrict__ bias,
                                float* __restrict__ y)
{
    extern __shared__ __align__(128) char dsm[];
    const uint32_t sbase = smem_u32(dsm);

    const int tid  = threadIdx.x;
    const int lane = tid & 31;
    const int wid  = tid >> 5;       // 0..7
    const int mBase = blockIdx.x * BM;   // m fast: both m-CTAs of an n share W in L2
    const int nBase = blockIdx.y * BN;

    const int wm = wid >> 2;   // 0..1  (64 m-rows)
    const int wn = wid & 3;    // 0..3  (32 n-cols)

    // ---- cp.async loader: 4 groups of 64 threads; thread -> 2 rows of one tile ----
    const int grp = tid >> 6;             // 0:A_hi 1:A_lo 2:B_hi 3:B_lo
    const int r0  = (tid & 63) * 2;
    const __nv_bfloat16* gsrc;
    if      (grp == 0) gsrc = g_x_hi + (size_t)(mBase + r0) * K_DIM;
    else if (grp == 1) gsrc = g_x_lo + (size_t)(mBase + r0) * K_DIM;
    else if (grp == 2) gsrc = g_w_hi + (size_t)(nBase + r0) * K_DIM;
    else               gsrc = g_w_lo + (size_t)(nBase + r0) * K_DIM;
    const uint32_t dstBase = (uint32_t)grp * SPLIT_BYTES + (uint32_t)r0 * RSTRIDE;

    // ---- ldmatrix per-thread offsets ----
    const uint32_t aOff = (uint32_t)(wm * 64 + (lane & 15)) * RSTRIDE + (lane >> 4) * 16;
    const uint32_t bOff = (uint32_t)(wn * 32 + (lane & 7) + ((lane >> 4) & 1) * 8) * RSTRIDE
                        + ((lane >> 3) & 1) * 16;

    float acc[4][4][4];
    #pragma unroll
    for (int i = 0; i < 4; ++i)
        #pragma unroll
        for (int j = 0; j < 4; ++j)
            #pragma unroll
            for (int r = 0; r < 4; ++r) acc[i][j][r] = 0.f;

    auto cpX = [&](int stage, int kt) {
        uint32_t dst = sbase + stage * STAGE_BYTES + dstBase;
        const __nv_bfloat16* src = gsrc + kt * KC;
        CP_ASYNC16(dst,      src);      CP_ASYNC16(dst + 16, src + 8);
        CP_ASYNC16(dst + 32, src + 16); CP_ASYNC16(dst + 48, src + 24);
        dst += RSTRIDE; src += K_DIM;
        CP_ASYNC16(dst,      src);      CP_ASYNC16(dst + 16, src + 8);
        CP_ASYNC16(dst + 32, src + 16); CP_ASYNC16(dst + 48, src + 24);
        CP_COMMIT();
    };

    auto doMMA = [&](int stage) {
        const uint32_t A_hi = sbase + stage * STAGE_BYTES;
        const uint32_t A_lo = A_hi + SPLIT_BYTES;
        const uint32_t B_hi = A_hi + 2 * SPLIT_BYTES;
        const uint32_t B_lo = A_hi + 3 * SPLIT_BYTES;
        #pragma unroll
        for (int k16 = 0; k16 < 2; ++k16) {
            uint32_t aH[4][4], aL[4][4], bH[4][2], bL[4][2];
            #pragma unroll
            for (int mf = 0; mf < 4; ++mf) {
                LDSM4(aH[mf][0], aH[mf][1], aH[mf][2], aH[mf][3],
                      A_hi + aOff + mf * (16 * RSTRIDE) + k16 * 32);
                LDSM4(aL[mf][0], aL[mf][1], aL[mf][2], aL[mf][3],
                      A_lo + aOff + mf * (16 * RSTRIDE) + k16 * 32);
            }
            #pragma unroll
            for (int p = 0; p < 2; ++p) {
                uint32_t q0, q1, q2, q3;
                LDSM4(q0, q1, q2, q3, B_hi + bOff + p * (16 * RSTRIDE) + k16 * 32);
                bH[2 * p][0] = q0; bH[2 * p][1] = q1;
                bH[2 * p + 1][0] = q2; bH[2 * p + 1][1] = q3;
                LDSM4(q0, q1, q2, q3, B_lo + bOff + p * (16 * RSTRIDE) + k16 * 32);
                bL[2 * p][0] = q0; bL[2 * p][1] = q1;
                bL[2 * p + 1][0] = q2; bL[2 * p + 1][1] = q3;
            }
            // term-major: 16 independent MMAs between accumulator reuses
            #pragma unroll
            for (int mf = 0; mf < 4; ++mf)
                #pragma unroll
                for (int nf = 0; nf < 4; ++nf) MMA(acc[mf][nf], aH[mf], bH[nf]);
            #pragma unroll
            for (int mf = 0; mf < 4; ++mf)
                #pragma unroll
                for (int nf = 0; nf < 4; ++nf) MMA(acc[mf][nf], aH[mf], bL[nf]);
            #pragma unroll
            for (int mf = 0; mf < 4; ++mf)
                #pragma unroll
                for (int nf = 0; nf < 4; ++nf) MMA(acc[mf][nf], aL[mf], bH[nf]);
        }
    };

    // ---- prologue: stages 0..3 in flight; stage 0 landed ----
    cpX(0, 0); cpX(1, 1); cpX(2, 2); cpX(3, 3);
    CP_WAIT3();
    __syncthreads();

    // ---- main loop: cp-issue + MMA + one wait + one barrier ----
    #pragma unroll 1
    for (int kt = 0; kt < NT; ++kt) {
        const int stage = kt % NSTAGE;
        if (kt + 4 < NT) cpX((kt + 4) % NSTAGE, kt + 4);
        else             CP_COMMIT();               // keep group counting aligned
        doMMA(stage);
        CP_WAIT3();                                 // stage kt+1 landed
        __syncthreads();
    }

    // ---- epilogue: y = acc + bias ----
    #pragma unroll
    for (int mf = 0; mf < 4; ++mf) {
        const int rr = mBase + wm * 64 + mf * 16 + (lane >> 2);
        #pragma unroll
        for (int nf = 0; nf < 4; ++nf) {
            const int c = nBase + wn * 32 + nf * 8 + (lane & 3) * 2;
            const float2 bv = *reinterpret_cast<const float2*>(bias + c);
            float2 o0 = make_float2(acc[mf][nf][0] + bv.x, acc[mf][nf][1] + bv.y);
            float2 o1 = make_float2(acc[mf][nf][2] + bv.x, acc[mf][nf][3] + bv.y);
            *reinterpret_cast<float2*>(y + (size_t)rr * OUT_DIM + c) = o0;
            *reinterpret_cast<float2*>(y + (size_t)(rr + 8) * OUT_DIM + c) = o1;
        }
    }
}

extern "C" void kernel_launch(void* const* d_in, const int* in_sizes, int n_in,
                              void* d_out, int out_size) {
    const float* x    = (const float*)d_in[0];
    const float* low  = (const float*)d_in[1];
    const float* high = (const float*)d_in[2];
    const float* W    = (const float*)d_in[3];
    const float* bias = (const float*)d_in[4];

    float* y        = (float*)d_out;
    float* low_out  = y + (size_t)B_DIM * OUT_DIM;
    float* high_out = low_out + OUT_DIM;

    cudaFuncSetAttribute(abstract_linear_mma_kernel,
                         cudaFuncAttributeMaxDynamicSharedMemorySize, DSMEM_BYTES);

    convert_x_kernel<<<(B_DIM * K_DIM) / (256 * 8), 256>>>(x);
    convert_w_kernel<<<OUT_DIM / 8, 256>>>(W, low, high, bias, low_out, high_out);

    dim3 grid(B_DIM / BM, OUT_DIM / BN);  // (2, 64): m fast for W L2 reuse
    abstract_linear_mma_kernel<<<grid, 256, DSMEM_BYTES>>>(bias, y);
}